// round 3
// baseline (speedup 1.0000x reference)
#include <cuda_runtime.h>
#include <math.h>

#define B_  64
#define T_  512
#define D_  512
#define H_  1024
#define G4  4096
#define M1  32768          // B_*T_
#define NBLK 128
#define RTH 256

// Recurrence smem: Bs[1024][32] floats + As2 double-buffer 2 x (64k x 64row dup)
#define R_SMEM_BYTES ((32768 + 16384) * 4)      // 192 KB
// Phase-1 smem: As2p 2x16x256 + Bsp 2x16x128
#define P1_SMEM_BYTES ((8192 + 4096) * 4)       // 48 KB

// ---------------------------------------------------------------------------
// Device globals (allocation-free scratch)
// ---------------------------------------------------------------------------
__device__ float g_xg[(size_t)M1 * G4];    // xg = x@Wx + b   (512 MB)
__device__ float g_hb[2][B_ * H_];         // double-buffered hidden state
__device__ unsigned g_cnt;                 // grid barrier counter
__device__ unsigned g_gen;                 // grid barrier generation

// ---------------------------------------------------------------------------
// f32x2 packed-FMA helpers
// ---------------------------------------------------------------------------
__device__ __forceinline__ void fma2(unsigned long long& d,
                                     unsigned long long a,
                                     unsigned long long b) {
    asm("fma.rn.f32x2 %0, %1, %2, %0;" : "+l"(d) : "l"(a), "l"(b));
}
__device__ __forceinline__ float2 unpack2(unsigned long long v) {
    float lo, hi;
    asm("mov.b64 {%0, %1}, %2;" : "=f"(lo), "=f"(hi) : "l"(v));
    return make_float2(lo, hi);
}

// ---------------------------------------------------------------------------
// Phase 1: xg[M1, G4] = x[M1, D] @ Wx[D, G4] + bias
// 128x128 tile, BK=16, 256 threads, 8x8 microtile, col-pair f32x2 acc,
// double-buffered smem (1 sync/chunk), dup-A in smem (zero pack MOVs)
// ---------------------------------------------------------------------------
__global__ void __launch_bounds__(256, 2)
gemm_xw(const float* __restrict__ x,
        const float* __restrict__ Wx,
        const float* __restrict__ bias) {
    extern __shared__ float sm[];
    float* As2p = sm;             // [2][16][128 dup] = 2*16*256 floats
    float* Bsp  = sm + 8192;      // [2][16][128]     = 2*16*128 floats

    const int bm = blockIdx.y;
    const int bn = blockIdx.x;
    const int tid = threadIdx.x;
    const int tx = tid & 15;          // col group: cols tx*8..+7
    const int ty = tid >> 4;          // row group: rows ty*8..+7
    const int ncol0 = bn * 128;

    // A staging coords: row = tid>>1 (0..127), kh = tid&1 (k-half of 8)
    const int rowA = tid >> 1;
    const int kh   = tid & 1;
    const int rpA  = rowA ^ (kh << 3);            // swizzled dup row
    const float* Aptr = x + (size_t)(bm * 128 + rowA) * D_ + kh * 8;

    // B staging coords: kr = tid>>4 (0..15), nc = (tid&15)*8
    const int kr = tid >> 4;
    const int nc = (tid & 15) * 8;
    const float* Bptr = Wx + (size_t)kr * G4 + ncol0 + nc;

    unsigned long long acc[8][4];
#pragma unroll
    for (int r = 0; r < 8; ++r)
#pragma unroll
        for (int c = 0; c < 4; ++c) acc[r][c] = 0ull;

    // reader bases for the two k-half swizzles
    const int baseR0 = (ty * 8);
    const int baseR1 = (ty * 8) ^ 8;

    // prologue: load + stage chunk 0
    float4 av0 = *(const float4*)(Aptr);
    float4 av1 = *(const float4*)(Aptr + 4);
    float4 bv0 = *(const float4*)(Bptr);
    float4 bv1 = *(const float4*)(Bptr + 4);
    {
        float va[8] = {av0.x, av0.y, av0.z, av0.w, av1.x, av1.y, av1.z, av1.w};
#pragma unroll
        for (int i = 0; i < 8; ++i)
            *(float2*)&As2p[((kh * 8 + i) * 128 + rpA) * 2] = make_float2(va[i], va[i]);
        *(float4*)&Bsp[kr * 128 + nc]     = bv0;
        *(float4*)&Bsp[kr * 128 + nc + 4] = bv1;
    }
    __syncthreads();

    for (int c = 0; c < 32; ++c) {
        if (c < 31) {
            const float* ap = Aptr + (c + 1) * 16;
            const float* bp = Bptr + (size_t)(c + 1) * 16 * G4;
            av0 = *(const float4*)(ap);
            av1 = *(const float4*)(ap + 4);
            bv0 = *(const float4*)(bp);
            bv1 = *(const float4*)(bp + 4);
        }
        const float* Ab = As2p + (c & 1) * 4096;
        const float* Bb = Bsp  + (c & 1) * 2048;
#pragma unroll
        for (int k = 0; k < 16; ++k) {
            const int base = (k < 8) ? baseR0 : baseR1;
            const float* ar = Ab + (k * 128 + base) * 2;
            ulonglong2 a01 = *(const ulonglong2*)(ar);
            ulonglong2 a23 = *(const ulonglong2*)(ar + 4);
            ulonglong2 a45 = *(const ulonglong2*)(ar + 8);
            ulonglong2 a67 = *(const ulonglong2*)(ar + 12);
            const float* br = Bb + k * 128 + tx * 8;
            ulonglong2 b01 = *(const ulonglong2*)(br);
            ulonglong2 b23 = *(const ulonglong2*)(br + 4);
            fma2(acc[0][0], a01.x, b01.x); fma2(acc[0][1], a01.x, b01.y);
            fma2(acc[0][2], a01.x, b23.x); fma2(acc[0][3], a01.x, b23.y);
            fma2(acc[1][0], a01.y, b01.x); fma2(acc[1][1], a01.y, b01.y);
            fma2(acc[1][2], a01.y, b23.x); fma2(acc[1][3], a01.y, b23.y);
            fma2(acc[2][0], a23.x, b01.x); fma2(acc[2][1], a23.x, b01.y);
            fma2(acc[2][2], a23.x, b23.x); fma2(acc[2][3], a23.x, b23.y);
            fma2(acc[3][0], a23.y, b01.x); fma2(acc[3][1], a23.y, b01.y);
            fma2(acc[3][2], a23.y, b23.x); fma2(acc[3][3], a23.y, b23.y);
            fma2(acc[4][0], a45.x, b01.x); fma2(acc[4][1], a45.x, b01.y);
            fma2(acc[4][2], a45.x, b23.x); fma2(acc[4][3], a45.x, b23.y);
            fma2(acc[5][0], a45.y, b01.x); fma2(acc[5][1], a45.y, b01.y);
            fma2(acc[5][2], a45.y, b23.x); fma2(acc[5][3], a45.y, b23.y);
            fma2(acc[6][0], a67.x, b01.x); fma2(acc[6][1], a67.x, b01.y);
            fma2(acc[6][2], a67.x, b23.x); fma2(acc[6][3], a67.x, b23.y);
            fma2(acc[7][0], a67.y, b01.x); fma2(acc[7][1], a67.y, b01.y);
            fma2(acc[7][2], a67.y, b23.x); fma2(acc[7][3], a67.y, b23.y);
        }
        if (c < 31) {
            float* Ab2 = As2p + ((c + 1) & 1) * 4096;
            float* Bb2 = Bsp  + ((c + 1) & 1) * 2048;
            float va[8] = {av0.x, av0.y, av0.z, av0.w, av1.x, av1.y, av1.z, av1.w};
#pragma unroll
            for (int i = 0; i < 8; ++i)
                *(float2*)&Ab2[((kh * 8 + i) * 128 + rpA) * 2] = make_float2(va[i], va[i]);
            *(float4*)&Bb2[kr * 128 + nc]     = bv0;
            *(float4*)&Bb2[kr * 128 + nc + 4] = bv1;
        }
        __syncthreads();
    }

    // Epilogue
    float bb[8];
#pragma unroll
    for (int j = 0; j < 8; ++j) bb[j] = bias[ncol0 + tx * 8 + j];

#pragma unroll
    for (int r = 0; r < 8; ++r) {
        float2 v0 = unpack2(acc[r][0]);
        float2 v1 = unpack2(acc[r][1]);
        float2 v2 = unpack2(acc[r][2]);
        float2 v3 = unpack2(acc[r][3]);
        size_t row = (size_t)(bm * 128 + ty * 8 + r);
        float* crow = g_xg + row * G4 + ncol0 + tx * 8;
        *(float4*)(crow)     = make_float4(v0.x + bb[0], v0.y + bb[1],
                                           v1.x + bb[2], v1.y + bb[3]);
        *(float4*)(crow + 4) = make_float4(v2.x + bb[4], v2.y + bb[5],
                                           v3.x + bb[6], v3.y + bb[7]);
    }
}

// ---------------------------------------------------------------------------
// Init
// ---------------------------------------------------------------------------
__global__ void init_state() {
    int idx = blockIdx.x * blockDim.x + threadIdx.x;
    g_hb[0][idx] = 0.0f;
    if (idx == 0) g_cnt = 0u;
}

// ---------------------------------------------------------------------------
// Grid-wide barrier (all NBLK blocks resident)
// ---------------------------------------------------------------------------
__device__ __forceinline__ void grid_barrier() {
    __threadfence();
    __syncthreads();
    if (threadIdx.x == 0) {
        volatile unsigned* vg = &g_gen;
        unsigned gen = *vg;
        if (atomicAdd(&g_cnt, 1u) == NBLK - 1) {
            atomicExch(&g_cnt, 0u);
            __threadfence();
            atomicAdd((unsigned*)&g_gen, 1u);
        } else {
            while (*vg == gen) { }
        }
    }
    __syncthreads();
}

// ---------------------------------------------------------------------------
// Persistent recurrence. Block bx owns 8 hidden cols (32 gate-cols,
// gate-interleaved c = jj*4+g). 256 threads. Per-thread microtile:
// 4 rows x 2 gate-cols, col-pair f32x2 acc (b loads directly as u64,
// a pre-duplicated in smem). Wh slice resident in smem all 512 steps.
// ---------------------------------------------------------------------------
__global__ void __launch_bounds__(RTH, 1)
lstm_persist(const float* __restrict__ Wh, float* __restrict__ out) {
    extern __shared__ float sm[];
    float* Bs  = sm;               // [1024][32]
    float* As2 = sm + 32768;       // 2 bufs x [64k][64 rows dup] = 2*8192 floats

    const int tid = threadIdx.x;
    const int j0 = blockIdx.x * 8;
    const int ty = tid >> 4;       // 0..15 -> rows ty*4..+3
    const int tx = tid & 15;       // cols 2tx, 2tx+1
    const int odd = tx & 1;

    // One-time Wh slice (gate-interleaved: col c -> hidden c>>2, gate c&3)
    for (int idx = tid; idx < 32768; idx += RTH) {
        int k = idx >> 5, c = idx & 31;
        Bs[idx] = Wh[(size_t)k * G4 + (c & 3) * H_ + j0 + (c >> 2)];
    }

    // staging coords: row = tid>>2 (0..63), skq = tid&3
    const int srow = tid >> 2;
    const int skq  = tid & 3;
    const int srp  = srow ^ (skq << 2);           // swizzled dup row (const!)

    // reader bases (s = (k>>2)&3)
    int baseS[4];
#pragma unroll
    for (int s = 0; s < 4; ++s) baseS[s] = (ty * 4) ^ (s << 2);

    // pointwise coords
    const int rbase = ty * 4 + (odd ? 2 : 0);
    const int j = j0 + (tx >> 1);

    float cc0 = 0.f, cc1 = 0.f;
    __syncthreads();

    for (int t = 0; t < T_; ++t) {
        const float* hin = g_hb[t & 1];
        float* hout = g_hb[(t + 1) & 1];

        // prefetch xg for the pointwise epilogue (independent of h)
        const float* xg0 = g_xg + ((size_t)rbase * T_ + t) * G4 + j;
        const float* xg1 = xg0 + (size_t)T_ * G4;
        float x_i0 = __ldcs(xg0);          float x_i1 = __ldcs(xg1);
        float x_f0 = __ldcs(xg0 + H_);     float x_f1 = __ldcs(xg1 + H_);
        float x_g0 = __ldcs(xg0 + 2*H_);   float x_g1 = __ldcs(xg1 + 2*H_);
        float x_o0 = __ldcs(xg0 + 3*H_);   float x_o1 = __ldcs(xg1 + 3*H_);

        unsigned long long ac0 = 0, ac1 = 0, ac2 = 0, ac3 = 0;

        // chunk 0: load + stage
        const float* hrow = hin + srow * H_;
        float4 pf0 = __ldcg((const float4*)(hrow + skq * 4));
        float4 pf1 = __ldcg((const float4*)(hrow + skq * 4 + 16));
        float4 pf2 = __ldcg((const float4*)(hrow + skq * 4 + 32));
        float4 pf3 = __ldcg((const float4*)(hrow + skq * 4 + 48));
        {
            float4 pv[4] = {pf0, pf1, pf2, pf3};
#pragma unroll
            for (int q = 0; q < 4; ++q) {
                int kb = skq * 4 + q * 16;
                float v[4] = {pv[q].x, pv[q].y, pv[q].z, pv[q].w};
#pragma unroll
                for (int jj = 0; jj < 4; ++jj)
                    *(float2*)&As2[((kb + jj) * 64 + srp) * 2] = make_float2(v[jj], v[jj]);
            }
        }
        __syncthreads();

        for (int kc = 0; kc < 16; ++kc) {
            if (kc < 15) {
                const float* hp = hrow + (kc + 1) * 64 + skq * 4;
                pf0 = __ldcg((const float4*)(hp));
                pf1 = __ldcg((const float4*)(hp + 16));
                pf2 = __ldcg((const float4*)(hp + 32));
                pf3 = __ldcg((const float4*)(hp + 48));
            }
            const float* cbuf = As2 + (kc & 1) * 8192;
            const float* bsp  = Bs + kc * 2048 + tx * 2;
#pragma unroll 4
            for (int ku = 0; ku < 4; ++ku) {
#pragma unroll
                for (int kk = 0; kk < 16; ++kk) {
                    const int k = ku * 16 + kk;
                    const int base = baseS[(kk >> 2) & 3];
                    const float* ar = cbuf + (k * 64 + base) * 2;
                    ulonglong2 a01 = *(const ulonglong2*)(ar);
                    ulonglong2 a23 = *(const ulonglong2*)(ar + 4);
                    unsigned long long bp = *(const unsigned long long*)(bsp + k * 32);
                    fma2(ac0, a01.x, bp);
                    fma2(ac1, a01.y, bp);
                    fma2(ac2, a23.x, bp);
                    fma2(ac3, a23.y, bp);
                }
            }
            if (kc < 15) {
                float* nbuf = As2 + ((kc + 1) & 1) * 8192;
                float4 pv[4] = {pf0, pf1, pf2, pf3};
#pragma unroll
                for (int q = 0; q < 4; ++q) {
                    int kb = skq * 4 + q * 16;
                    float v[4] = {pv[q].x, pv[q].y, pv[q].z, pv[q].w};
#pragma unroll
                    for (int jj = 0; jj < 4; ++jj)
                        *(float2*)&nbuf[((kb + jj) * 64 + srp) * 2] = make_float2(v[jj], v[jj]);
                }
            }
            __syncthreads();
        }

        // Re-join gate pairs: even tx holds (i,f), odd tx holds (g,o)
        unsigned long long o0 = __shfl_xor_sync(0xffffffffu, ac0, 1);
        unsigned long long o1 = __shfl_xor_sync(0xffffffffu, ac1, 1);
        unsigned long long o2 = __shfl_xor_sync(0xffffffffu, ac2, 1);
        unsigned long long o3 = __shfl_xor_sync(0xffffffffu, ac3, 1);
        unsigned long long if0 = odd ? o2  : ac0;
        unsigned long long if1 = odd ? o3  : ac1;
        unsigned long long go0 = odd ? ac2 : o0;
        unsigned long long go1 = odd ? ac3 : o1;

        {
            float2 vif = unpack2(if0);
            float2 vgo = unpack2(go0);
            float vi = vif.x + x_i0, vf = vif.y + x_f0;
            float vg = vgo.x + x_g0, vo = vgo.y + x_o0;
            float si = 1.0f / (1.0f + expf(-vi));
            float sf = 1.0f / (1.0f + expf(-vf));
            float tg = tanhf(vg);
            float so = 1.0f / (1.0f + expf(-vo));
            float c = sf * cc0 + si * tg;
            cc0 = c;
            float h = so * tanhf(c);
            hout[rbase * H_ + j] = h;
            out[((size_t)rbase * T_ + t) * H_ + j] = h;
        }
        {
            float2 vif = unpack2(if1);
            float2 vgo = unpack2(go1);
            float vi = vif.x + x_i1, vf = vif.y + x_f1;
            float vg = vgo.x + x_g1, vo = vgo.y + x_o1;
            float si = 1.0f / (1.0f + expf(-vi));
            float sf = 1.0f / (1.0f + expf(-vf));
            float tg = tanhf(vg);
            float so = 1.0f / (1.0f + expf(-vo));
            float c = sf * cc1 + si * tg;
            cc1 = c;
            float h = so * tanhf(c);
            hout[(rbase + 1) * H_ + j] = h;
            out[((size_t)(rbase + 1) * T_ + t) * H_ + j] = h;
        }

        if (t < T_ - 1) grid_barrier();
    }
}

// ---------------------------------------------------------------------------
// Launch: 3 graph nodes
// ---------------------------------------------------------------------------
extern "C" void kernel_launch(void* const* d_in, const int* in_sizes, int n_in,
                              void* d_out, int out_size) {
    const float* x    = (const float*)d_in[0];   // [B, T, D]
    const float* Wx   = (const float*)d_in[1];   // [D, 4H]
    const float* Wh   = (const float*)d_in[2];   // [H, 4H]
    const float* bias = (const float*)d_in[3];   // [4H]
    float* out = (float*)d_out;                  // [B, T, H]

    cudaFuncSetAttribute(lstm_persist,
                         cudaFuncAttributeMaxDynamicSharedMemorySize, R_SMEM_BYTES);
    cudaFuncSetAttribute(gemm_xw,
                         cudaFuncAttributeMaxDynamicSharedMemorySize, P1_SMEM_BYTES);

    dim3 g1(G4 / 128, M1 / 128);                 // (32, 256)
    gemm_xw<<<g1, 256, P1_SMEM_BYTES>>>(x, Wx, bias);
    init_state<<<256, 256>>>();
    lstm_persist<<<NBLK, RTH, R_SMEM_BYTES>>>(Wh, out);
}

// round 4
// speedup vs baseline: 1.0015x; 1.0015x over previous
#include <cuda_runtime.h>
#include <math.h>

#define B_  64
#define T_  512
#define D_  512
#define H_  1024
#define G4  4096
#define M1  32768          // B_*T_
#define NBLK 128
#define RTH 256

// Recurrence smem: Bs[1024][32] floats + As2 double-buffer 2 x (64k x 64row dup)
#define R_SMEM_BYTES ((32768 + 16384) * 4)      // 192 KB
// Phase-1 smem: As2p 2x16x256 + Bsp 2x16x128
#define P1_SMEM_BYTES ((8192 + 4096) * 4)       // 48 KB

// ---------------------------------------------------------------------------
// Device globals (allocation-free scratch)
// ---------------------------------------------------------------------------
__device__ float g_xg[(size_t)M1 * G4];    // xg = x@Wx + b   (512 MB)
__device__ float g_hb[2][B_ * H_];         // double-buffered hidden state
__device__ unsigned g_cnt;                 // grid barrier counter
__device__ unsigned g_gen;                 // grid barrier generation

// ---------------------------------------------------------------------------
// f32x2 packed-FMA helpers
// ---------------------------------------------------------------------------
__device__ __forceinline__ void fma2(unsigned long long& d,
                                     unsigned long long a,
                                     unsigned long long b) {
    asm("fma.rn.f32x2 %0, %1, %2, %0;" : "+l"(d) : "l"(a), "l"(b));
}
__device__ __forceinline__ float2 unpack2(unsigned long long v) {
    float lo, hi;
    asm("mov.b64 {%0, %1}, %2;" : "=f"(lo), "=f"(hi) : "l"(v));
    return make_float2(lo, hi);
}

// ---------------------------------------------------------------------------
// Phase 1: xg[M1, G4] = x[M1, D] @ Wx[D, G4] + bias
// 128x128 tile, BK=16, 256 threads, 8x8 microtile, col-pair f32x2 acc,
// double-buffered smem (1 sync/chunk), dup-A in smem (zero pack MOVs)
// ---------------------------------------------------------------------------
__global__ void __launch_bounds__(256, 2)
gemm_xw(const float* __restrict__ x,
        const float* __restrict__ Wx,
        const float* __restrict__ bias) {
    extern __shared__ float sm[];
    float* As2p = sm;             // [2][16][128 dup] = 2*16*256 floats
    float* Bsp  = sm + 8192;      // [2][16][128]     = 2*16*128 floats

    const int bm = blockIdx.y;
    const int bn = blockIdx.x;
    const int tid = threadIdx.x;
    const int tx = tid & 15;          // col group: cols tx*8..+7
    const int ty = tid >> 4;          // row group: rows ty*8..+7
    const int ncol0 = bn * 128;

    // A staging coords: row = tid>>1 (0..127), kh = tid&1 (k-half of 8)
    const int rowA = tid >> 1;
    const int kh   = tid & 1;
    const int rpA  = rowA ^ (kh << 3);            // swizzled dup row
    const float* Aptr = x + (size_t)(bm * 128 + rowA) * D_ + kh * 8;

    // B staging coords: kr = tid>>4 (0..15), nc = (tid&15)*8
    const int kr = tid >> 4;
    const int nc = (tid & 15) * 8;
    const float* Bptr = Wx + (size_t)kr * G4 + ncol0 + nc;

    unsigned long long acc[8][4];
#pragma unroll
    for (int r = 0; r < 8; ++r)
#pragma unroll
        for (int c = 0; c < 4; ++c) acc[r][c] = 0ull;

    // reader bases for the two k-half swizzles
    const int baseR0 = (ty * 8);
    const int baseR1 = (ty * 8) ^ 8;

    // prologue: load + stage chunk 0
    float4 av0 = *(const float4*)(Aptr);
    float4 av1 = *(const float4*)(Aptr + 4);
    float4 bv0 = *(const float4*)(Bptr);
    float4 bv1 = *(const float4*)(Bptr + 4);
    {
        float va[8] = {av0.x, av0.y, av0.z, av0.w, av1.x, av1.y, av1.z, av1.w};
#pragma unroll
        for (int i = 0; i < 8; ++i)
            *(float2*)&As2p[((kh * 8 + i) * 128 + rpA) * 2] = make_float2(va[i], va[i]);
        *(float4*)&Bsp[kr * 128 + nc]     = bv0;
        *(float4*)&Bsp[kr * 128 + nc + 4] = bv1;
    }
    __syncthreads();

    for (int c = 0; c < 32; ++c) {
        if (c < 31) {
            const float* ap = Aptr + (c + 1) * 16;
            const float* bp = Bptr + (size_t)(c + 1) * 16 * G4;
            av0 = *(const float4*)(ap);
            av1 = *(const float4*)(ap + 4);
            bv0 = *(const float4*)(bp);
            bv1 = *(const float4*)(bp + 4);
        }
        const float* Ab = As2p + (c & 1) * 4096;
        const float* Bb = Bsp  + (c & 1) * 2048;
#pragma unroll
        for (int k = 0; k < 16; ++k) {
            const int base = (k < 8) ? baseR0 : baseR1;
            const float* ar = Ab + (k * 128 + base) * 2;
            ulonglong2 a01 = *(const ulonglong2*)(ar);
            ulonglong2 a23 = *(const ulonglong2*)(ar + 4);
            ulonglong2 a45 = *(const ulonglong2*)(ar + 8);
            ulonglong2 a67 = *(const ulonglong2*)(ar + 12);
            const float* br = Bb + k * 128 + tx * 8;
            ulonglong2 b01 = *(const ulonglong2*)(br);
            ulonglong2 b23 = *(const ulonglong2*)(br + 4);
            fma2(acc[0][0], a01.x, b01.x); fma2(acc[0][1], a01.x, b01.y);
            fma2(acc[0][2], a01.x, b23.x); fma2(acc[0][3], a01.x, b23.y);
            fma2(acc[1][0], a01.y, b01.x); fma2(acc[1][1], a01.y, b01.y);
            fma2(acc[1][2], a01.y, b23.x); fma2(acc[1][3], a01.y, b23.y);
            fma2(acc[2][0], a23.x, b01.x); fma2(acc[2][1], a23.x, b01.y);
            fma2(acc[2][2], a23.x, b23.x); fma2(acc[2][3], a23.x, b23.y);
            fma2(acc[3][0], a23.y, b01.x); fma2(acc[3][1], a23.y, b01.y);
            fma2(acc[3][2], a23.y, b23.x); fma2(acc[3][3], a23.y, b23.y);
            fma2(acc[4][0], a45.x, b01.x); fma2(acc[4][1], a45.x, b01.y);
            fma2(acc[4][2], a45.x, b23.x); fma2(acc[4][3], a45.x, b23.y);
            fma2(acc[5][0], a45.y, b01.x); fma2(acc[5][1], a45.y, b01.y);
            fma2(acc[5][2], a45.y, b23.x); fma2(acc[5][3], a45.y, b23.y);
            fma2(acc[6][0], a67.x, b01.x); fma2(acc[6][1], a67.x, b01.y);
            fma2(acc[6][2], a67.x, b23.x); fma2(acc[6][3], a67.x, b23.y);
            fma2(acc[7][0], a67.y, b01.x); fma2(acc[7][1], a67.y, b01.y);
            fma2(acc[7][2], a67.y, b23.x); fma2(acc[7][3], a67.y, b23.y);
        }
        if (c < 31) {
            float* Ab2 = As2p + ((c + 1) & 1) * 4096;
            float* Bb2 = Bsp  + ((c + 1) & 1) * 2048;
            float va[8] = {av0.x, av0.y, av0.z, av0.w, av1.x, av1.y, av1.z, av1.w};
#pragma unroll
            for (int i = 0; i < 8; ++i)
                *(float2*)&Ab2[((kh * 8 + i) * 128 + rpA) * 2] = make_float2(va[i], va[i]);
            *(float4*)&Bb2[kr * 128 + nc]     = bv0;
            *(float4*)&Bb2[kr * 128 + nc + 4] = bv1;
        }
        __syncthreads();
    }

    // Epilogue
    float bb[8];
#pragma unroll
    for (int j = 0; j < 8; ++j) bb[j] = bias[ncol0 + tx * 8 + j];

#pragma unroll
    for (int r = 0; r < 8; ++r) {
        float2 v0 = unpack2(acc[r][0]);
        float2 v1 = unpack2(acc[r][1]);
        float2 v2 = unpack2(acc[r][2]);
        float2 v3 = unpack2(acc[r][3]);
        size_t row = (size_t)(bm * 128 + ty * 8 + r);
        float* crow = g_xg + row * G4 + ncol0 + tx * 8;
        *(float4*)(crow)     = make_float4(v0.x + bb[0], v0.y + bb[1],
                                           v1.x + bb[2], v1.y + bb[3]);
        *(float4*)(crow + 4) = make_float4(v2.x + bb[4], v2.y + bb[5],
                                           v3.x + bb[6], v3.y + bb[7]);
    }
}

// ---------------------------------------------------------------------------
// Init
// ---------------------------------------------------------------------------
__global__ void init_state() {
    int idx = blockIdx.x * blockDim.x + threadIdx.x;
    g_hb[0][idx] = 0.0f;
    if (idx == 0) g_cnt = 0u;
}

// ---------------------------------------------------------------------------
// Grid-wide barrier (all NBLK blocks resident)
// ---------------------------------------------------------------------------
__device__ __forceinline__ void grid_barrier() {
    __threadfence();
    __syncthreads();
    if (threadIdx.x == 0) {
        volatile unsigned* vg = &g_gen;
        unsigned gen = *vg;
        if (atomicAdd(&g_cnt, 1u) == NBLK - 1) {
            atomicExch(&g_cnt, 0u);
            __threadfence();
            atomicAdd((unsigned*)&g_gen, 1u);
        } else {
            while (*vg == gen) { }
        }
    }
    __syncthreads();
}

// ---------------------------------------------------------------------------
// Persistent recurrence. Block bx owns 8 hidden cols (32 gate-cols,
// gate-interleaved c = jj*4+g). 256 threads. Per-thread microtile:
// 4 rows x 2 gate-cols, col-pair f32x2 acc (b loads directly as u64,
// a pre-duplicated in smem). Wh slice resident in smem all 512 steps.
// ---------------------------------------------------------------------------
__global__ void __launch_bounds__(RTH, 1)
lstm_persist(const float* __restrict__ Wh, float* __restrict__ out) {
    extern __shared__ float sm[];
    float* Bs  = sm;               // [1024][32]
    float* As2 = sm + 32768;       // 2 bufs x [64k][64 rows dup] = 2*8192 floats

    const int tid = threadIdx.x;
    const int j0 = blockIdx.x * 8;
    const int ty = tid >> 4;       // 0..15 -> rows ty*4..+3
    const int tx = tid & 15;       // cols 2tx, 2tx+1
    const int odd = tx & 1;

    // One-time Wh slice (gate-interleaved: col c -> hidden c>>2, gate c&3)
    for (int idx = tid; idx < 32768; idx += RTH) {
        int k = idx >> 5, c = idx & 31;
        Bs[idx] = Wh[(size_t)k * G4 + (c & 3) * H_ + j0 + (c >> 2)];
    }

    // staging coords: row = tid>>2 (0..63), skq = tid&3
    const int srow = tid >> 2;
    const int skq  = tid & 3;
    const int srp  = srow ^ (skq << 2);           // swizzled dup row (const!)

    // reader bases (s = (k>>2)&3)
    int baseS[4];
#pragma unroll
    for (int s = 0; s < 4; ++s) baseS[s] = (ty * 4) ^ (s << 2);

    // pointwise coords
    const int rbase = ty * 4 + (odd ? 2 : 0);
    const int j = j0 + (tx >> 1);

    float cc0 = 0.f, cc1 = 0.f;
    __syncthreads();

    for (int t = 0; t < T_; ++t) {
        const float* hin = g_hb[t & 1];
        float* hout = g_hb[(t + 1) & 1];

        // prefetch xg for the pointwise epilogue (independent of h)
        const float* xg0 = g_xg + ((size_t)rbase * T_ + t) * G4 + j;
        const float* xg1 = xg0 + (size_t)T_ * G4;
        float x_i0 = __ldcs(xg0);          float x_i1 = __ldcs(xg1);
        float x_f0 = __ldcs(xg0 + H_);     float x_f1 = __ldcs(xg1 + H_);
        float x_g0 = __ldcs(xg0 + 2*H_);   float x_g1 = __ldcs(xg1 + 2*H_);
        float x_o0 = __ldcs(xg0 + 3*H_);   float x_o1 = __ldcs(xg1 + 3*H_);

        unsigned long long ac0 = 0, ac1 = 0, ac2 = 0, ac3 = 0;

        // chunk 0: load + stage
        const float* hrow = hin + srow * H_;
        float4 pf0 = __ldcg((const float4*)(hrow + skq * 4));
        float4 pf1 = __ldcg((const float4*)(hrow + skq * 4 + 16));
        float4 pf2 = __ldcg((const float4*)(hrow + skq * 4 + 32));
        float4 pf3 = __ldcg((const float4*)(hrow + skq * 4 + 48));
        {
            float4 pv[4] = {pf0, pf1, pf2, pf3};
#pragma unroll
            for (int q = 0; q < 4; ++q) {
                int kb = skq * 4 + q * 16;
                float v[4] = {pv[q].x, pv[q].y, pv[q].z, pv[q].w};
#pragma unroll
                for (int jj = 0; jj < 4; ++jj)
                    *(float2*)&As2[((kb + jj) * 64 + srp) * 2] = make_float2(v[jj], v[jj]);
            }
        }
        __syncthreads();

        for (int kc = 0; kc < 16; ++kc) {
            if (kc < 15) {
                const float* hp = hrow + (kc + 1) * 64 + skq * 4;
                pf0 = __ldcg((const float4*)(hp));
                pf1 = __ldcg((const float4*)(hp + 16));
                pf2 = __ldcg((const float4*)(hp + 32));
                pf3 = __ldcg((const float4*)(hp + 48));
            }
            const float* cbuf = As2 + (kc & 1) * 8192;
            const float* bsp  = Bs + kc * 2048 + tx * 2;
#pragma unroll 4
            for (int ku = 0; ku < 4; ++ku) {
#pragma unroll
                for (int kk = 0; kk < 16; ++kk) {
                    const int k = ku * 16 + kk;
                    const int base = baseS[(kk >> 2) & 3];
                    const float* ar = cbuf + (k * 64 + base) * 2;
                    ulonglong2 a01 = *(const ulonglong2*)(ar);
                    ulonglong2 a23 = *(const ulonglong2*)(ar + 4);
                    unsigned long long bp = *(const unsigned long long*)(bsp + k * 32);
                    fma2(ac0, a01.x, bp);
                    fma2(ac1, a01.y, bp);
                    fma2(ac2, a23.x, bp);
                    fma2(ac3, a23.y, bp);
                }
            }
            if (kc < 15) {
                float* nbuf = As2 + ((kc + 1) & 1) * 8192;
                float4 pv[4] = {pf0, pf1, pf2, pf3};
#pragma unroll
                for (int q = 0; q < 4; ++q) {
                    int kb = skq * 4 + q * 16;
                    float v[4] = {pv[q].x, pv[q].y, pv[q].z, pv[q].w};
#pragma unroll
                    for (int jj = 0; jj < 4; ++jj)
                        *(float2*)&nbuf[((kb + jj) * 64 + srp) * 2] = make_float2(v[jj], v[jj]);
                }
            }
            __syncthreads();
        }

        // Re-join gate pairs: even tx holds (i,f), odd tx holds (g,o)
        unsigned long long o0 = __shfl_xor_sync(0xffffffffu, ac0, 1);
        unsigned long long o1 = __shfl_xor_sync(0xffffffffu, ac1, 1);
        unsigned long long o2 = __shfl_xor_sync(0xffffffffu, ac2, 1);
        unsigned long long o3 = __shfl_xor_sync(0xffffffffu, ac3, 1);
        unsigned long long if0 = odd ? o2  : ac0;
        unsigned long long if1 = odd ? o3  : ac1;
        unsigned long long go0 = odd ? ac2 : o0;
        unsigned long long go1 = odd ? ac3 : o1;

        {
            float2 vif = unpack2(if0);
            float2 vgo = unpack2(go0);
            float vi = vif.x + x_i0, vf = vif.y + x_f0;
            float vg = vgo.x + x_g0, vo = vgo.y + x_o0;
            float si = 1.0f / (1.0f + expf(-vi));
            float sf = 1.0f / (1.0f + expf(-vf));
            float tg = tanhf(vg);
            float so = 1.0f / (1.0f + expf(-vo));
            float c = sf * cc0 + si * tg;
            cc0 = c;
            float h = so * tanhf(c);
            hout[rbase * H_ + j] = h;
            out[((size_t)rbase * T_ + t) * H_ + j] = h;
        }
        {
            float2 vif = unpack2(if1);
            float2 vgo = unpack2(go1);
            float vi = vif.x + x_i1, vf = vif.y + x_f1;
            float vg = vgo.x + x_g1, vo = vgo.y + x_o1;
            float si = 1.0f / (1.0f + expf(-vi));
            float sf = 1.0f / (1.0f + expf(-vf));
            float tg = tanhf(vg);
            float so = 1.0f / (1.0f + expf(-vo));
            float c = sf * cc1 + si * tg;
            cc1 = c;
            float h = so * tanhf(c);
            hout[(rbase + 1) * H_ + j] = h;
            out[((size_t)(rbase + 1) * T_ + t) * H_ + j] = h;
        }

        if (t < T_ - 1) grid_barrier();
    }
}

// ---------------------------------------------------------------------------
// Launch: 3 graph nodes
// ---------------------------------------------------------------------------
extern "C" void kernel_launch(void* const* d_in, const int* in_sizes, int n_in,
                              void* d_out, int out_size) {
    const float* x    = (const float*)d_in[0];   // [B, T, D]
    const float* Wx   = (const float*)d_in[1];   // [D, 4H]
    const float* Wh   = (const float*)d_in[2];   // [H, 4H]
    const float* bias = (const float*)d_in[3];   // [4H]
    float* out = (float*)d_out;                  // [B, T, H]

    cudaFuncSetAttribute(lstm_persist,
                         cudaFuncAttributeMaxDynamicSharedMemorySize, R_SMEM_BYTES);
    cudaFuncSetAttribute(gemm_xw,
                         cudaFuncAttributeMaxDynamicSharedMemorySize, P1_SMEM_BYTES);

    dim3 g1(G4 / 128, M1 / 128);                 // (32, 256)
    gemm_xw<<<g1, 256, P1_SMEM_BYTES>>>(x, Wx, bias);
    init_state<<<256, 256>>>();
    lstm_persist<<<NBLK, RTH, R_SMEM_BYTES>>>(Wh, out);
}